// round 12
// baseline (speedup 1.0000x reference)
#include <cuda_runtime.h>
#include <cuda_bf16.h>
#include <math.h>
#include <stdint.h>

#define Bb 4
#define Ll 1024
#define Ee 1024
#define Hh 16
#define DHh 64
#define TOPKk 32

// -------- scratch (no allocs allowed) --------
__device__ float g_q [Bb*Ll*Ee];
__device__ float g_k [Bb*Ll*Ee];
__device__ float g_v [Bb*Ll*Ee];
__device__ float g_ao[Bb*Ll*Ee];

// v path (side stream)
__device__ __nv_bfloat16 g_vs1[Bb*Ll*Ee];
__device__ __nv_bfloat16 g_vs2[Bb*Ll*Ee];
__device__ __nv_bfloat16 g_wv1[Ee*Ee];
__device__ __nv_bfloat16 g_wv2[Ee*Ee];
__device__ __nv_bfloat16 g_wo1[Ee*Ee];
__device__ __nv_bfloat16 g_wo2[Ee*Ee];

// attention filter path (bf16 copies of q/k)
__device__ __nv_bfloat16 g_qb[Bb*Ll*Ee];
__device__ __nv_bfloat16 g_kb[Bb*Ll*Ee];

// ============================================================
// Scalar fp32 GEMM — exact round-1 version (bit-identical)
// ============================================================
#define GBM 128
#define GBN 128
#define GBK 16

__global__ __launch_bounds__(256) void gemm_nt_bias(
    const float* __restrict__ X, const float* __restrict__ W,
    const float* __restrict__ bias, float* __restrict__ out,
    int M, int N, int K)
{
    __shared__ float As[GBK][GBM];
    __shared__ float Bs[GBK][GBN];

    const int tid = threadIdx.x;
    const int bm = blockIdx.y * GBM;
    const int bn = blockIdx.x * GBN;

    const int tr = (tid / 16) * 8;
    const int tc = (tid % 16) * 8;

    const int arow  = tid >> 2;
    const int acol4 = tid & 3;

    float acc[8][8] = {};

    for (int k0 = 0; k0 < K; k0 += GBK) {
        #pragma unroll
        for (int r = 0; r < 2; r++) {
            int row = arow + r * 64;
            float4 v = *(const float4*)(X + (size_t)(bm + row) * K + k0 + acol4 * 4);
            As[acol4*4+0][row] = v.x;
            As[acol4*4+1][row] = v.y;
            As[acol4*4+2][row] = v.z;
            As[acol4*4+3][row] = v.w;
        }
        #pragma unroll
        for (int r = 0; r < 2; r++) {
            int row = arow + r * 64;
            float4 v = *(const float4*)(W + (size_t)(bn + row) * K + k0 + acol4 * 4);
            Bs[acol4*4+0][row] = v.x;
            Bs[acol4*4+1][row] = v.y;
            Bs[acol4*4+2][row] = v.z;
            Bs[acol4*4+3][row] = v.w;
        }
        __syncthreads();

        #pragma unroll
        for (int k = 0; k < GBK; k++) {
            float ra[8], rb[8];
            #pragma unroll
            for (int i = 0; i < 8; i++) ra[i] = As[k][tr + i];
            #pragma unroll
            for (int j = 0; j < 8; j++) rb[j] = Bs[k][tc + j];
            #pragma unroll
            for (int i = 0; i < 8; i++)
                #pragma unroll
                for (int j = 0; j < 8; j++)
                    acc[i][j] = fmaf(ra[i], rb[j], acc[i][j]);
        }
        __syncthreads();
    }

    #pragma unroll
    for (int i = 0; i < 8; i++) {
        #pragma unroll
        for (int j = 0; j < 8; j++) {
            out[(size_t)(bm + tr + i) * N + bn + tc + j] = acc[i][j] + bias[bn + tc + j];
        }
    }
}

// ============================================================
// casts / splits
// ============================================================
__global__ void split2_kernel(const float* __restrict__ src,
                              __nv_bfloat16* __restrict__ p1,
                              __nv_bfloat16* __restrict__ p2, int n)
{
    int i = blockIdx.x * blockDim.x + threadIdx.x;
    if (i >= n) return;
    float x = src[i];
    __nv_bfloat16 b1 = __float2bfloat16_rn(x);
    float r1 = x - __bfloat162float(b1);
    p1[i] = b1;
    p2[i] = __float2bfloat16_rn(r1);
}

__global__ void cast_bf16_kernel(const float* __restrict__ src,
                                 __nv_bfloat16* __restrict__ dst, int n)
{
    int i = blockIdx.x * blockDim.x + threadIdx.x;
    if (i < n) dst[i] = __float2bfloat16_rn(src[i]);
}

// ============================================================
// mma helpers
// ============================================================
__device__ __forceinline__ void mma16816(
    float& d0, float& d1, float& d2, float& d3,
    uint32_t a0, uint32_t a1, uint32_t a2, uint32_t a3,
    uint32_t b0, uint32_t b1)
{
    asm volatile(
        "mma.sync.aligned.m16n8k16.row.col.f32.bf16.bf16.f32 "
        "{%0,%1,%2,%3}, {%4,%5,%6,%7}, {%8,%9}, {%0,%1,%2,%3};"
        : "+f"(d0), "+f"(d1), "+f"(d2), "+f"(d3)
        : "r"(a0), "r"(a1), "r"(a2), "r"(a3), "r"(b0), "r"(b1));
}
__device__ __forceinline__ void ldsm_x4(uint32_t& r0, uint32_t& r1,
                                        uint32_t& r2, uint32_t& r3, uint32_t saddr)
{
    asm volatile("ldmatrix.sync.aligned.m8n8.x4.shared.b16 {%0,%1,%2,%3}, [%4];"
        : "=r"(r0), "=r"(r1), "=r"(r2), "=r"(r3) : "r"(saddr));
}
__device__ __forceinline__ uint32_t smem_u32(const void* p) {
    uint32_t a;
    asm("{ .reg .u64 t; cvta.to.shared.u64 t, %1; cvt.u32.u64 %0, t; }" : "=r"(a) : "l"(p));
    return a;
}
__device__ __forceinline__ void cp_async16(uint32_t saddr, const void* g) {
    asm volatile("cp.async.cg.shared.global [%0], [%1], 16;" :: "r"(saddr), "l"(g));
}
#define CP_COMMIT() asm volatile("cp.async.commit_group;" ::: "memory")
#define CP_WAIT(n)  asm volatile("cp.async.wait_group %0;" :: "n"(n) : "memory")

#define TK 1024
#define TN 1024
#define NCHUNK (TK / 32)
#define SROWB 80
#define TILE_B (128 * SROWB)
#define STAGE_B (4 * TILE_B)
#define TG_SMEM (2 * STAGE_B)

// ============================================================
// 3-term bf16x2 GEMM (v / out projections) — round-7 version
// ============================================================
__global__ __launch_bounds__(256, 2) void gemm_bf16x2_mma(
    const __nv_bfloat16* __restrict__ A1, const __nv_bfloat16* __restrict__ A2,
    const __nv_bfloat16* __restrict__ B1, const __nv_bfloat16* __restrict__ B2,
    const float* __restrict__ bias, float* __restrict__ out)
{
    extern __shared__ char smem[];
    const uint32_t smem_b = smem_u32(smem);

    const int tid = threadIdx.x;
    const int wid = tid >> 5;
    const int lane = tid & 31;
    const int g  = lane >> 2;
    const int tg = lane & 3;

    const int bm = blockIdx.y * 128;
    const int bn = blockIdx.x * 128;
    const int wm = (wid >> 1) * 32;
    const int wn = (wid & 1) * 64;

    const uint32_t lrow = (uint32_t)(lane & 15);
    const uint32_t lcol = (uint32_t)((lane >> 4) << 3);

    const __nv_bfloat16* gp[4] = {A1, A2, B1, B2};
    const int gbase[4] = {bm, bm, bn, bn};

    float acc[2][8][4] = {};

    for (int kc = 0; kc < NCHUNK + 1; kc++) {
        if (kc < NCHUNK) {
            const int k0 = kc * 32;
            const uint32_t stage_off = (uint32_t)(kc & 1) * STAGE_B;
            #pragma unroll
            for (int it = 0; it < 8; it++) {
                int c = tid + it * 256;
                int t = c >> 9;
                int rem = c & 511;
                int row = rem >> 2;
                int seg = rem & 3;
                uint32_t sa = smem_b + stage_off + (uint32_t)t * TILE_B
                            + (uint32_t)row * SROWB + (uint32_t)seg * 16;
                const __nv_bfloat16* gsrc = gp[t] + (size_t)(gbase[t] + row) * TK + k0 + seg * 8;
                cp_async16(sa, gsrc);
            }
            CP_COMMIT();
        }
        if (kc == 0) continue;

        if (kc < NCHUNK) { CP_WAIT(1); } else { CP_WAIT(0); }
        __syncthreads();

        const uint32_t st_u = smem_b + (uint32_t)((kc - 1) & 1) * STAGE_B;

        #pragma unroll
        for (int ks = 0; ks < 2; ks++) {
            const uint32_t coff = (uint32_t)(ks * 16) * 2 + lcol * 2;

            uint32_t af[2][2][4];
            #pragma unroll
            for (int p = 0; p < 2; p++)
                #pragma unroll
                for (int mt = 0; mt < 2; mt++) {
                    uint32_t addr = st_u + (uint32_t)p * TILE_B
                                  + ((uint32_t)(wm + mt * 16) + lrow) * SROWB + coff;
                    ldsm_x4(af[p][mt][0], af[p][mt][1], af[p][mt][2], af[p][mt][3], addr);
                }
            #pragma unroll
            for (int np = 0; np < 4; np++) {
                uint32_t bf[2][2][2];
                #pragma unroll
                for (int p = 0; p < 2; p++) {
                    uint32_t addr = st_u + (uint32_t)(2 + p) * TILE_B
                                  + ((uint32_t)(wn + np * 16) + lrow) * SROWB + coff;
                    ldsm_x4(bf[p][0][0], bf[p][1][0], bf[p][0][1], bf[p][1][1], addr);
                }
                #pragma unroll
                for (int ntl = 0; ntl < 2; ntl++) {
                    const int nt = np * 2 + ntl;
                    #pragma unroll
                    for (int mt = 0; mt < 2; mt++) {
                        mma16816(acc[mt][nt][0], acc[mt][nt][1], acc[mt][nt][2], acc[mt][nt][3],
                                 af[0][mt][0], af[0][mt][1], af[0][mt][2], af[0][mt][3],
                                 bf[0][ntl][0], bf[0][ntl][1]);
                        mma16816(acc[mt][nt][0], acc[mt][nt][1], acc[mt][nt][2], acc[mt][nt][3],
                                 af[0][mt][0], af[0][mt][1], af[0][mt][2], af[0][mt][3],
                                 bf[1][ntl][0], bf[1][ntl][1]);
                        mma16816(acc[mt][nt][0], acc[mt][nt][1], acc[mt][nt][2], acc[mt][nt][3],
                                 af[1][mt][0], af[1][mt][1], af[1][mt][2], af[1][mt][3],
                                 bf[0][ntl][0], bf[0][ntl][1]);
                    }
                }
            }
        }
        __syncthreads();
    }

    #pragma unroll
    for (int mt = 0; mt < 2; mt++) {
        #pragma unroll
        for (int nt = 0; nt < 8; nt++) {
            int m0 = bm + wm + mt * 16 + g;
            int n0 = bn + wn + nt * 8 + tg * 2;
            float b0 = bias[n0], b1 = bias[n0 + 1];
            float2 lo = make_float2(acc[mt][nt][0] + b0, acc[mt][nt][1] + b1);
            float2 hi = make_float2(acc[mt][nt][2] + b0, acc[mt][nt][3] + b1);
            *(float2*)(out + (size_t)m0 * TN + n0)       = lo;
            *(float2*)(out + (size_t)(m0 + 8) * TN + n0) = hi;
        }
    }
}

// ============================================================
// Fused attention: per block (128-query tile, bh).
//   per 128-key tile: bf16 mma approx scores -> smem fp32,
//   128 scan threads keep running approx top-32 and gate exact
//   rescoring (R8-identical fmaf chain) at aMin_run - margin.
// Selection provably identical to the R8 full scan.
// ============================================================
#define KMARGIN 0.0625f
#define FROW 72                    // bf16 row stride (144 B)
#define FROWB 144

// smem layout (float units)
#define F_SQF 0                        // [128][65] fp32
#define F_SQB (F_SQF + 128*65)         // [128][72] bf16 = 4608 floats
#define F_SKB (F_SQB + 128*FROW/2)     // [128][72] bf16
#define F_SS  (F_SKB + 128*FROW/2)     // [128][129] fp32
#define F_SAV (F_SS + 128*129)         // [128][33] fp32
#define F_STV (F_SAV + 128*33)
#define F_STI (F_STV + 128*33)
#define F_FLOATS (F_STI + 128*33)      // 46720 floats = 186880 B

__global__ __launch_bounds__(256) void fused_attn_kernel(
    const float* __restrict__ gq, const float* __restrict__ gk,
    const float* __restrict__ gv,
    const __nv_bfloat16* __restrict__ qb, const __nv_bfloat16* __restrict__ kb,
    float* __restrict__ gao)
{
    extern __shared__ float sm[];
    float* sQf = sm + F_SQF;
    char*  sQb = (char*)(sm + F_SQB);
    char*  sKb = (char*)(sm + F_SKB);
    float* sS  = sm + F_SS;
    float* sAV = sm + F_SAV;
    float* sTV = sm + F_STV;
    int*   sTI = (int*)(sm + F_STI);

    const int tid = threadIdx.x;
    const int wid = tid >> 5;
    const int lane = tid & 31;
    const int g  = lane >> 2;
    const int tg = lane & 3;

    const int bh = blockIdx.y;
    const int b  = bh >> 4;
    const int h  = bh & 15;
    const int l0 = blockIdx.x * 128;

    // load q fp32 (for exact rescoring): 128 q x 8 segs of 8 floats = 1024 units
    #pragma unroll
    for (int it = 0; it < 4; it++) {
        int idx = tid + it * 256;        // 0..1023
        int q = idx >> 3;                // 0..127
        int d4 = idx & 7;                // 0..7
        float4 v  = *(const float4*)(gq + ((size_t)(b * Ll + l0 + q)) * Ee + h * 64 + d4 * 8);
        float4 v2 = *(const float4*)(gq + ((size_t)(b * Ll + l0 + q)) * Ee + h * 64 + d4 * 8 + 4);
        sQf[q * 65 + d4 * 8 + 0] = v.x;  sQf[q * 65 + d4 * 8 + 1] = v.y;
        sQf[q * 65 + d4 * 8 + 2] = v.z;  sQf[q * 65 + d4 * 8 + 3] = v.w;
        sQf[q * 65 + d4 * 8 + 4] = v2.x; sQf[q * 65 + d4 * 8 + 5] = v2.y;
        sQf[q * 65 + d4 * 8 + 6] = v2.z; sQf[q * 65 + d4 * 8 + 7] = v2.w;
    }
    // load q bf16 tile
    #pragma unroll
    for (int it = 0; it < 4; it++) {
        int c = tid + it * 256;          // 0..1023 (128 rows x 8 segs)
        int row = c >> 3;
        int seg = c & 7;
        *(uint4*)(sQb + row * FROWB + seg * 16) =
            *(const uint4*)(qb + ((size_t)(b * Ll + l0 + row)) * Ee + h * 64 + seg * 8);
    }
    if (tid < 128) {
        #pragma unroll
        for (int j = 0; j < TOPKk; j++) {
            sAV[tid * 33 + j] = -INFINITY;
            sTV[tid * 33 + j] = -INFINITY;
            sTI[tid * 33 + j] = 0;
        }
    }
    __syncthreads();

    const uint32_t sQbu = smem_u32(sQb);
    const uint32_t sKbu = smem_u32(sKb);
    const int wm = (wid >> 1) * 32;
    const int wn = (wid & 1) * 64;
    const uint32_t lrow = (uint32_t)(lane & 15);
    const uint32_t lcol16 = (uint32_t)((lane >> 4) * 16);

    float aMin = -INFINITY;
    int   aPos = 0;
    float eMin = -INFINITY;
    int   ePos = 0;

    for (int kt = 0; kt < 8; kt++) {
        // load k tile bf16
        #pragma unroll
        for (int it = 0; it < 4; it++) {
            int c = tid + it * 256;
            int row = c >> 3;
            int seg = c & 7;
            *(uint4*)(sKb + row * FROWB + seg * 16) =
                *(const uint4*)(kb + ((size_t)(b * Ll + kt * 128 + row)) * Ee + h * 64 + seg * 8);
        }
        __syncthreads();

        // mma: 128x128 approx scores
        float acc[2][8][4] = {};
        #pragma unroll
        for (int ks = 0; ks < 4; ks++) {
            const uint32_t coff = (uint32_t)ks * 32 + lcol16;
            uint32_t af[2][4];
            #pragma unroll
            for (int mt = 0; mt < 2; mt++) {
                uint32_t addr = sQbu + ((uint32_t)(wm + mt * 16) + lrow) * FROWB + coff;
                ldsm_x4(af[mt][0], af[mt][1], af[mt][2], af[mt][3], addr);
            }
            #pragma unroll
            for (int np = 0; np < 4; np++) {
                uint32_t bf[2][2];
                uint32_t addr = sKbu + ((uint32_t)(wn + np * 16) + lrow) * FROWB + coff;
                ldsm_x4(bf[0][0], bf[1][0], bf[0][1], bf[1][1], addr);
                #pragma unroll
                for (int ntl = 0; ntl < 2; ntl++) {
                    const int nt = np * 2 + ntl;
                    #pragma unroll
                    for (int mt = 0; mt < 2; mt++)
                        mma16816(acc[mt][nt][0], acc[mt][nt][1], acc[mt][nt][2], acc[mt][nt][3],
                                 af[mt][0], af[mt][1], af[mt][2], af[mt][3],
                                 bf[ntl][0], bf[ntl][1]);
                }
            }
        }
        #pragma unroll
        for (int mt = 0; mt < 2; mt++) {
            #pragma unroll
            for (int nt = 0; nt < 8; nt++) {
                int m0 = wm + mt * 16 + g;
                int n0 = wn + nt * 8 + tg * 2;
                sS[m0 * 129 + n0]           = acc[mt][nt][0] * 0.125f;
                sS[m0 * 129 + n0 + 1]       = acc[mt][nt][1] * 0.125f;
                sS[(m0 + 8) * 129 + n0]     = acc[mt][nt][2] * 0.125f;
                sS[(m0 + 8) * 129 + n0 + 1] = acc[mt][nt][3] * 0.125f;
            }
        }
        __syncthreads();

        // scan: approx top-32 + gated exact rescoring (tid<128, 1 per query)
        if (tid < 128) {
            #pragma unroll 1
            for (int kk = 0; kk < 128; kk++) {
                float a = sS[tid * 129 + kk];
                if (a > aMin) {
                    sAV[tid * 33 + aPos] = a;
                    float mn = sAV[tid * 33];
                    int   mp = 0;
                    #pragma unroll
                    for (int j = 1; j < TOPKk; j++) {
                        float v = sAV[tid * 33 + j];
                        if (v < mn) { mn = v; mp = j; }
                    }
                    aMin = mn; aPos = mp;
                }
                if (a >= aMin - KMARGIN) {
                    const int key = kt * 128 + kk;
                    const float4* kr = (const float4*)(gk + ((size_t)(b * Ll + key)) * Ee + h * 64);
                    float acs = 0.0f;
                    #pragma unroll
                    for (int d4 = 0; d4 < 16; d4++) {
                        float4 kv = kr[d4];
                        acs = fmaf(sQf[tid * 65 + d4 * 4 + 0], kv.x, acs);
                        acs = fmaf(sQf[tid * 65 + d4 * 4 + 1], kv.y, acs);
                        acs = fmaf(sQf[tid * 65 + d4 * 4 + 2], kv.z, acs);
                        acs = fmaf(sQf[tid * 65 + d4 * 4 + 3], kv.w, acs);
                    }
                    float s = acs * 0.125f;
                    if (s > eMin) {
                        sTV[tid * 33 + ePos] = s;
                        sTI[tid * 33 + ePos] = key;
                        float mn = sTV[tid * 33];
                        int   mp = 0;
                        #pragma unroll
                        for (int j = 1; j < TOPKk; j++) {
                            float v = sTV[tid * 33 + j];
                            if (v < mn) { mn = v; mp = j; }
                        }
                        eMin = mn; ePos = mp;
                    }
                }
            }
        }
        __syncthreads();
    }

    // epilogue: warp per query softmax + V gather (R8-identical)
    const int warp = tid >> 5;
    for (int qi = warp; qi < 128; qi += 8) {
        float v  = sTV[qi * 33 + lane];
        int   ki = sTI[qi * 33 + lane];

        float mx = v;
        #pragma unroll
        for (int o = 16; o; o >>= 1) mx = fmaxf(mx, __shfl_xor_sync(0xffffffffu, mx, o));
        float e = expf(v - mx);
        float se = e;
        #pragma unroll
        for (int o = 16; o; o >>= 1) se += __shfl_xor_sync(0xffffffffu, se, o);
        float w = e / se;

        float a0 = 0.f, a1 = 0.f;
        #pragma unroll
        for (int j = 0; j < TOPKk; j++) {
            float wj = __shfl_sync(0xffffffffu, w, j);
            int   kj = __shfl_sync(0xffffffffu, ki, j);
            const float* vr = gv + ((size_t)(b * Ll + kj)) * Ee + h * 64;
            a0 = fmaf(wj, vr[lane],      a0);
            a1 = fmaf(wj, vr[lane + 32], a1);
        }
        float* op = gao + ((size_t)(b * Ll + l0 + qi)) * Ee + h * 64;
        op[lane]      = a0;
        op[lane + 32] = a1;
    }
}

// ============================================================
extern "C" void kernel_launch(void* const* d_in, const int* in_sizes, int n_in,
                              void* d_out, int out_size)
{
    const float* Q  = (const float*)d_in[0];
    const float* K_ = (const float*)d_in[1];
    const float* V  = (const float*)d_in[2];
    const float* Wq = (const float*)d_in[3];
    const float* bq = (const float*)d_in[4];
    const float* Wk = (const float*)d_in[5];
    const float* bk = (const float*)d_in[6];
    const float* Wv = (const float*)d_in[7];
    const float* bv = (const float*)d_in[8];
    const float* Wo = (const float*)d_in[9];
    const float* bo = (const float*)d_in[10];
    float* out = (float*)d_out;

    float *gq, *gk, *gv, *gao;
    cudaGetSymbolAddress((void**)&gq,  g_q);
    cudaGetSymbolAddress((void**)&gk,  g_k);
    cudaGetSymbolAddress((void**)&gv,  g_v);
    cudaGetSymbolAddress((void**)&gao, g_ao);
    __nv_bfloat16 *vs1, *vs2, *wv1, *wv2, *wo1, *wo2, *qb, *kb;
    cudaGetSymbolAddress((void**)&vs1, g_vs1);
    cudaGetSymbolAddress((void**)&vs2, g_vs2);
    cudaGetSymbolAddress((void**)&wv1, g_wv1);
    cudaGetSymbolAddress((void**)&wv2, g_wv2);
    cudaGetSymbolAddress((void**)&wo1, g_wo1);
    cudaGetSymbolAddress((void**)&wo2, g_wo2);
    cudaGetSymbolAddress((void**)&qb,  g_qb);
    cudaGetSymbolAddress((void**)&kb,  g_kb);

    static cudaStream_t sV = nullptr;
    static cudaEvent_t eFork = nullptr, eV = nullptr;
    if (sV == nullptr) {
        cudaStreamCreateWithFlags(&sV, cudaStreamNonBlocking);
        cudaEventCreateWithFlags(&eFork, cudaEventDisableTiming);
        cudaEventCreateWithFlags(&eV, cudaEventDisableTiming);
    }

    const int M = Bb * Ll;   // 4096
    const int N = Ee;        // 1024
    const int K = Ee;        // 1024

    dim3 gblock(256);
    dim3 ggrid(N / GBN, M / GBM);
    dim3 tgrid(N / 128, M / 128);

    cudaFuncSetAttribute(gemm_bf16x2_mma,
                         cudaFuncAttributeMaxDynamicSharedMemorySize, TG_SMEM);
    const int faSmem = F_FLOATS * sizeof(float);   // ~182.5 KB
    cudaFuncSetAttribute(fused_attn_kernel,
                         cudaFuncAttributeMaxDynamicSharedMemorySize, faSmem);

    // ---- fork: v-path on side stream ----
    cudaEventRecord(eFork, 0);
    cudaStreamWaitEvent(sV, eFork, 0);

    split2_kernel<<<(M*K + 255)/256, 256, 0, sV>>>(V,  vs1, vs2, M*K);
    split2_kernel<<<(N*K + 255)/256, 256, 0, sV>>>(Wv, wv1, wv2, N*K);
    gemm_bf16x2_mma<<<tgrid, 256, TG_SMEM, sV>>>(vs1, vs2, wv1, wv2, bv, gv);
    split2_kernel<<<(N*K + 255)/256, 256, 0, sV>>>(Wo, wo1, wo2, N*K);
    cudaEventRecord(eV, sV);

    // ---- main: q, k projections (scalar fp32, bit-identical) ----
    gemm_nt_bias<<<ggrid, gblock>>>(Q,  Wq, bq, gq, M, N, K);
    gemm_nt_bias<<<ggrid, gblock>>>(K_, Wk, bk, gk, M, N, K);

    // bf16 casts for the approx filter
    cast_bf16_kernel<<<(M*K + 255)/256, 256>>>(gq, qb, M*K);
    cast_bf16_kernel<<<(M*K + 255)/256, 256>>>(gk, kb, M*K);

    // join: fused attention needs v from the side stream
    cudaStreamWaitEvent(0, eV, 0);

    dim3 agrid(Ll / 128, Bb * Hh);   // (8, 64)
    fused_attn_kernel<<<agrid, 256, faSmem>>>(gq, gk, gv, qb, kb, gao);

    // ---- output projection (3-term bf16x2) ----
    split2_kernel<<<(M*K + 255)/256, 256>>>(gao, vs1, vs2, M*K);
    gemm_bf16x2_mma<<<tgrid, 256, TG_SMEM>>>(vs1, vs2, wo1, wo2, bo, out);
}

// round 13
// speedup vs baseline: 1.4596x; 1.4596x over previous
#include <cuda_runtime.h>
#include <cuda_bf16.h>
#include <math.h>
#include <stdint.h>

#define Bb 4
#define Ll 1024
#define Ee 1024
#define Hh 16
#define DHh 64
#define TOPKk 32

// -------- scratch (no allocs allowed) --------
__device__ float g_q [Bb*Ll*Ee];
__device__ float g_k [Bb*Ll*Ee];
__device__ float g_v [Bb*Ll*Ee];
__device__ float g_ao[Bb*Ll*Ee];

// v path (side stream)
__device__ __nv_bfloat16 g_vs1[Bb*Ll*Ee];
__device__ __nv_bfloat16 g_vs2[Bb*Ll*Ee];
__device__ __nv_bfloat16 g_wv1[Ee*Ee];
__device__ __nv_bfloat16 g_wv2[Ee*Ee];
__device__ __nv_bfloat16 g_wo1[Ee*Ee];
__device__ __nv_bfloat16 g_wo2[Ee*Ee];

// attention filter path (bf16 copies of q/k)
__device__ __nv_bfloat16 g_qb[Bb*Ll*Ee];
__device__ __nv_bfloat16 g_kb[Bb*Ll*Ee];

// ============================================================
// Scalar fp32 GEMM — exact round-1 version (bit-identical)
// ============================================================
#define GBM 128
#define GBN 128
#define GBK 16

__global__ __launch_bounds__(256) void gemm_nt_bias(
    const float* __restrict__ X, const float* __restrict__ W,
    const float* __restrict__ bias, float* __restrict__ out,
    int M, int N, int K)
{
    __shared__ float As[GBK][GBM];
    __shared__ float Bs[GBK][GBN];

    const int tid = threadIdx.x;
    const int bm = blockIdx.y * GBM;
    const int bn = blockIdx.x * GBN;

    const int tr = (tid / 16) * 8;
    const int tc = (tid % 16) * 8;

    const int arow  = tid >> 2;
    const int acol4 = tid & 3;

    float acc[8][8] = {};

    for (int k0 = 0; k0 < K; k0 += GBK) {
        #pragma unroll
        for (int r = 0; r < 2; r++) {
            int row = arow + r * 64;
            float4 v = *(const float4*)(X + (size_t)(bm + row) * K + k0 + acol4 * 4);
            As[acol4*4+0][row] = v.x;
            As[acol4*4+1][row] = v.y;
            As[acol4*4+2][row] = v.z;
            As[acol4*4+3][row] = v.w;
        }
        #pragma unroll
        for (int r = 0; r < 2; r++) {
            int row = arow + r * 64;
            float4 v = *(const float4*)(W + (size_t)(bn + row) * K + k0 + acol4 * 4);
            Bs[acol4*4+0][row] = v.x;
            Bs[acol4*4+1][row] = v.y;
            Bs[acol4*4+2][row] = v.z;
            Bs[acol4*4+3][row] = v.w;
        }
        __syncthreads();

        #pragma unroll
        for (int k = 0; k < GBK; k++) {
            float ra[8], rb[8];
            #pragma unroll
            for (int i = 0; i < 8; i++) ra[i] = As[k][tr + i];
            #pragma unroll
            for (int j = 0; j < 8; j++) rb[j] = Bs[k][tc + j];
            #pragma unroll
            for (int i = 0; i < 8; i++)
                #pragma unroll
                for (int j = 0; j < 8; j++)
                    acc[i][j] = fmaf(ra[i], rb[j], acc[i][j]);
        }
        __syncthreads();
    }

    #pragma unroll
    for (int i = 0; i < 8; i++) {
        #pragma unroll
        for (int j = 0; j < 8; j++) {
            out[(size_t)(bm + tr + i) * N + bn + tc + j] = acc[i][j] + bias[bn + tc + j];
        }
    }
}

// ============================================================
// casts / splits
// ============================================================
__global__ void split2_kernel(const float* __restrict__ src,
                              __nv_bfloat16* __restrict__ p1,
                              __nv_bfloat16* __restrict__ p2, int n)
{
    int i = blockIdx.x * blockDim.x + threadIdx.x;
    if (i >= n) return;
    float x = src[i];
    __nv_bfloat16 b1 = __float2bfloat16_rn(x);
    float r1 = x - __bfloat162float(b1);
    p1[i] = b1;
    p2[i] = __float2bfloat16_rn(r1);
}

__global__ void cast_bf16_kernel(const float* __restrict__ src,
                                 __nv_bfloat16* __restrict__ dst, int n)
{
    int i = blockIdx.x * blockDim.x + threadIdx.x;
    if (i < n) dst[i] = __float2bfloat16_rn(src[i]);
}

// ============================================================
// mma helpers
// ============================================================
__device__ __forceinline__ void mma16816(
    float& d0, float& d1, float& d2, float& d3,
    uint32_t a0, uint32_t a1, uint32_t a2, uint32_t a3,
    uint32_t b0, uint32_t b1)
{
    asm volatile(
        "mma.sync.aligned.m16n8k16.row.col.f32.bf16.bf16.f32 "
        "{%0,%1,%2,%3}, {%4,%5,%6,%7}, {%8,%9}, {%0,%1,%2,%3};"
        : "+f"(d0), "+f"(d1), "+f"(d2), "+f"(d3)
        : "r"(a0), "r"(a1), "r"(a2), "r"(a3), "r"(b0), "r"(b1));
}
__device__ __forceinline__ void ldsm_x4(uint32_t& r0, uint32_t& r1,
                                        uint32_t& r2, uint32_t& r3, uint32_t saddr)
{
    asm volatile("ldmatrix.sync.aligned.m8n8.x4.shared.b16 {%0,%1,%2,%3}, [%4];"
        : "=r"(r0), "=r"(r1), "=r"(r2), "=r"(r3) : "r"(saddr));
}
__device__ __forceinline__ uint32_t smem_u32(const void* p) {
    uint32_t a;
    asm("{ .reg .u64 t; cvta.to.shared.u64 t, %1; cvt.u32.u64 %0, t; }" : "=r"(a) : "l"(p));
    return a;
}
__device__ __forceinline__ void cp_async16(uint32_t saddr, const void* g) {
    asm volatile("cp.async.cg.shared.global [%0], [%1], 16;" :: "r"(saddr), "l"(g));
}
#define CP_COMMIT() asm volatile("cp.async.commit_group;" ::: "memory")
#define CP_WAIT(n)  asm volatile("cp.async.wait_group %0;" :: "n"(n) : "memory")

#define TK 1024
#define TN 1024
#define NCHUNK (TK / 32)
#define SROWB 80
#define TILE_B (128 * SROWB)
#define STAGE_B (4 * TILE_B)
#define TG_SMEM (2 * STAGE_B)

// ============================================================
// 3-term bf16x2 GEMM (v / out projections) — round-7 version
// ============================================================
__global__ __launch_bounds__(256, 2) void gemm_bf16x2_mma(
    const __nv_bfloat16* __restrict__ A1, const __nv_bfloat16* __restrict__ A2,
    const __nv_bfloat16* __restrict__ B1, const __nv_bfloat16* __restrict__ B2,
    const float* __restrict__ bias, float* __restrict__ out)
{
    extern __shared__ char smem[];
    const uint32_t smem_b = smem_u32(smem);

    const int tid = threadIdx.x;
    const int wid = tid >> 5;
    const int lane = tid & 31;
    const int g  = lane >> 2;
    const int tg = lane & 3;

    const int bm = blockIdx.y * 128;
    const int bn = blockIdx.x * 128;
    const int wm = (wid >> 1) * 32;
    const int wn = (wid & 1) * 64;

    const uint32_t lrow = (uint32_t)(lane & 15);
    const uint32_t lcol = (uint32_t)((lane >> 4) << 3);

    const __nv_bfloat16* gp[4] = {A1, A2, B1, B2};
    const int gbase[4] = {bm, bm, bn, bn};

    float acc[2][8][4] = {};

    for (int kc = 0; kc < NCHUNK + 1; kc++) {
        if (kc < NCHUNK) {
            const int k0 = kc * 32;
            const uint32_t stage_off = (uint32_t)(kc & 1) * STAGE_B;
            #pragma unroll
            for (int it = 0; it < 8; it++) {
                int c = tid + it * 256;
                int t = c >> 9;
                int rem = c & 511;
                int row = rem >> 2;
                int seg = rem & 3;
                uint32_t sa = smem_b + stage_off + (uint32_t)t * TILE_B
                            + (uint32_t)row * SROWB + (uint32_t)seg * 16;
                const __nv_bfloat16* gsrc = gp[t] + (size_t)(gbase[t] + row) * TK + k0 + seg * 8;
                cp_async16(sa, gsrc);
            }
            CP_COMMIT();
        }
        if (kc == 0) continue;

        if (kc < NCHUNK) { CP_WAIT(1); } else { CP_WAIT(0); }
        __syncthreads();

        const uint32_t st_u = smem_b + (uint32_t)((kc - 1) & 1) * STAGE_B;

        #pragma unroll
        for (int ks = 0; ks < 2; ks++) {
            const uint32_t coff = (uint32_t)(ks * 16) * 2 + lcol * 2;

            uint32_t af[2][2][4];
            #pragma unroll
            for (int p = 0; p < 2; p++)
                #pragma unroll
                for (int mt = 0; mt < 2; mt++) {
                    uint32_t addr = st_u + (uint32_t)p * TILE_B
                                  + ((uint32_t)(wm + mt * 16) + lrow) * SROWB + coff;
                    ldsm_x4(af[p][mt][0], af[p][mt][1], af[p][mt][2], af[p][mt][3], addr);
                }
            #pragma unroll
            for (int np = 0; np < 4; np++) {
                uint32_t bf[2][2][2];
                #pragma unroll
                for (int p = 0; p < 2; p++) {
                    uint32_t addr = st_u + (uint32_t)(2 + p) * TILE_B
                                  + ((uint32_t)(wn + np * 16) + lrow) * SROWB + coff;
                    ldsm_x4(bf[p][0][0], bf[p][1][0], bf[p][0][1], bf[p][1][1], addr);
                }
                #pragma unroll
                for (int ntl = 0; ntl < 2; ntl++) {
                    const int nt = np * 2 + ntl;
                    #pragma unroll
                    for (int mt = 0; mt < 2; mt++) {
                        mma16816(acc[mt][nt][0], acc[mt][nt][1], acc[mt][nt][2], acc[mt][nt][3],
                                 af[0][mt][0], af[0][mt][1], af[0][mt][2], af[0][mt][3],
                                 bf[0][ntl][0], bf[0][ntl][1]);
                        mma16816(acc[mt][nt][0], acc[mt][nt][1], acc[mt][nt][2], acc[mt][nt][3],
                                 af[0][mt][0], af[0][mt][1], af[0][mt][2], af[0][mt][3],
                                 bf[1][ntl][0], bf[1][ntl][1]);
                        mma16816(acc[mt][nt][0], acc[mt][nt][1], acc[mt][nt][2], acc[mt][nt][3],
                                 af[1][mt][0], af[1][mt][1], af[1][mt][2], af[1][mt][3],
                                 bf[0][ntl][0], bf[0][ntl][1]);
                    }
                }
            }
        }
        __syncthreads();
    }

    #pragma unroll
    for (int mt = 0; mt < 2; mt++) {
        #pragma unroll
        for (int nt = 0; nt < 8; nt++) {
            int m0 = bm + wm + mt * 16 + g;
            int n0 = bn + wn + nt * 8 + tg * 2;
            float b0 = bias[n0], b1 = bias[n0 + 1];
            float2 lo = make_float2(acc[mt][nt][0] + b0, acc[mt][nt][1] + b1);
            float2 hi = make_float2(acc[mt][nt][2] + b0, acc[mt][nt][3] + b1);
            *(float2*)(out + (size_t)m0 * TN + n0)       = lo;
            *(float2*)(out + (size_t)(m0 + 8) * TN + n0) = hi;
        }
    }
}

// ============================================================
// Fused attention v2: per block (128-query tile, bh).
//   per 128-key tile:
//     - bf16 mma approx scores -> smem fp32
//     - scan: running approx top-32; gated keys RECORDED to a
//       per-query candidate list (no divergent heavy body)
//     - phase-b: walk candidate list in order; exact rescore
//       (R8-identical fmaf chain) + insert-replace-min.
// Gate decisions + insert order identical to R12 => output
// bit-identical to R8.
// ============================================================
#define KMARGIN 0.0625f
#define FROWB 144

// smem layout (float units)
#define F_SQF 0                        // [128][65] fp32
#define F_SQB (F_SQF + 128*65)         // [128] rows x 144B bf16 = 4608 floats
#define F_SKB (F_SQB + 128*36)         // same
#define F_SS  (F_SKB + 128*36)         // [128][129] fp32
#define F_SAV (F_SS + 128*129)         // [128][33] fp32
#define F_STV (F_SAV + 128*33)
#define F_STI (F_STV + 128*33)
#define F_CAND (F_STI + 128*33)        // [128] rows x 132B uint8 = 4224 floats
#define F_FLOATS (F_CAND + 128*33)     // 50944 floats = 203776 B

__global__ __launch_bounds__(256) void fused_attn_kernel(
    const float* __restrict__ gq, const float* __restrict__ gk,
    const float* __restrict__ gv,
    const __nv_bfloat16* __restrict__ qb, const __nv_bfloat16* __restrict__ kb,
    float* __restrict__ gao)
{
    extern __shared__ float sm[];
    float* sQf = sm + F_SQF;
    char*  sQb = (char*)(sm + F_SQB);
    char*  sKb = (char*)(sm + F_SKB);
    float* sS  = sm + F_SS;
    float* sAV = sm + F_SAV;
    float* sTV = sm + F_STV;
    int*   sTI = (int*)(sm + F_STI);
    unsigned char* sCand = (unsigned char*)(sm + F_CAND);

    const int tid = threadIdx.x;
    const int wid = tid >> 5;
    const int lane = tid & 31;
    const int g  = lane >> 2;
    const int tg = lane & 3;

    const int bh = blockIdx.y;
    const int b  = bh >> 4;
    const int h  = bh & 15;
    const int l0 = blockIdx.x * 128;

    // load q fp32 (for exact rescoring): 128 q x 8 segs of 8 floats = 1024 units
    #pragma unroll
    for (int it = 0; it < 4; it++) {
        int idx = tid + it * 256;        // 0..1023
        int q = idx >> 3;                // 0..127
        int d4 = idx & 7;                // 0..7
        float4 v  = *(const float4*)(gq + ((size_t)(b * Ll + l0 + q)) * Ee + h * 64 + d4 * 8);
        float4 v2 = *(const float4*)(gq + ((size_t)(b * Ll + l0 + q)) * Ee + h * 64 + d4 * 8 + 4);
        sQf[q * 65 + d4 * 8 + 0] = v.x;  sQf[q * 65 + d4 * 8 + 1] = v.y;
        sQf[q * 65 + d4 * 8 + 2] = v.z;  sQf[q * 65 + d4 * 8 + 3] = v.w;
        sQf[q * 65 + d4 * 8 + 4] = v2.x; sQf[q * 65 + d4 * 8 + 5] = v2.y;
        sQf[q * 65 + d4 * 8 + 6] = v2.z; sQf[q * 65 + d4 * 8 + 7] = v2.w;
    }
    // load q bf16 tile
    #pragma unroll
    for (int it = 0; it < 4; it++) {
        int c = tid + it * 256;          // 0..1023 (128 rows x 8 segs)
        int row = c >> 3;
        int seg = c & 7;
        *(uint4*)(sQb + row * FROWB + seg * 16) =
            *(const uint4*)(qb + ((size_t)(b * Ll + l0 + row)) * Ee + h * 64 + seg * 8);
    }
    if (tid < 128) {
        #pragma unroll
        for (int j = 0; j < TOPKk; j++) {
            sAV[tid * 33 + j] = -INFINITY;
            sTV[tid * 33 + j] = -INFINITY;
            sTI[tid * 33 + j] = 0;
        }
    }
    __syncthreads();

    const uint32_t sQbu = smem_u32(sQb);
    const uint32_t sKbu = smem_u32(sKb);
    const int wm = (wid >> 1) * 32;
    const int wn = (wid & 1) * 64;
    const uint32_t lrow = (uint32_t)(lane & 15);
    const uint32_t lcol16 = (uint32_t)((lane >> 4) * 16);

    float aMin = -INFINITY;
    int   aPos = 0;
    float eMin = -INFINITY;
    int   ePos = 0;

    for (int kt = 0; kt < 8; kt++) {
        // load k tile bf16
        #pragma unroll
        for (int it = 0; it < 4; it++) {
            int c = tid + it * 256;
            int row = c >> 3;
            int seg = c & 7;
            *(uint4*)(sKb + row * FROWB + seg * 16) =
                *(const uint4*)(kb + ((size_t)(b * Ll + kt * 128 + row)) * Ee + h * 64 + seg * 8);
        }
        __syncthreads();

        // mma: 128x128 approx scores
        float acc[2][8][4] = {};
        #pragma unroll
        for (int ks = 0; ks < 4; ks++) {
            const uint32_t coff = (uint32_t)ks * 32 + lcol16;
            uint32_t af[2][4];
            #pragma unroll
            for (int mt = 0; mt < 2; mt++) {
                uint32_t addr = sQbu + ((uint32_t)(wm + mt * 16) + lrow) * FROWB + coff;
                ldsm_x4(af[mt][0], af[mt][1], af[mt][2], af[mt][3], addr);
            }
            #pragma unroll
            for (int np = 0; np < 4; np++) {
                uint32_t bf[2][2];
                uint32_t addr = sKbu + ((uint32_t)(wn + np * 16) + lrow) * FROWB + coff;
                ldsm_x4(bf[0][0], bf[1][0], bf[0][1], bf[1][1], addr);
                #pragma unroll
                for (int ntl = 0; ntl < 2; ntl++) {
                    const int nt = np * 2 + ntl;
                    #pragma unroll
                    for (int mt = 0; mt < 2; mt++)
                        mma16816(acc[mt][nt][0], acc[mt][nt][1], acc[mt][nt][2], acc[mt][nt][3],
                                 af[mt][0], af[mt][1], af[mt][2], af[mt][3],
                                 bf[ntl][0], bf[ntl][1]);
                }
            }
        }
        #pragma unroll
        for (int mt = 0; mt < 2; mt++) {
            #pragma unroll
            for (int nt = 0; nt < 8; nt++) {
                int m0 = wm + mt * 16 + g;
                int n0 = wn + nt * 8 + tg * 2;
                sS[m0 * 129 + n0]           = acc[mt][nt][0] * 0.125f;
                sS[m0 * 129 + n0 + 1]       = acc[mt][nt][1] * 0.125f;
                sS[(m0 + 8) * 129 + n0]     = acc[mt][nt][2] * 0.125f;
                sS[(m0 + 8) * 129 + n0 + 1] = acc[mt][nt][3] * 0.125f;
            }
        }
        __syncthreads();

        if (tid < 128) {
            // phase-a: approx top-32 scan; record gated candidates (no heavy body)
            int clen = 0;
            #pragma unroll 1
            for (int kk = 0; kk < 128; kk++) {
                float a = sS[tid * 129 + kk];
                if (a > aMin) {
                    sAV[tid * 33 + aPos] = a;
                    float mn = sAV[tid * 33];
                    int   mp = 0;
                    #pragma unroll
                    for (int j = 1; j < TOPKk; j++) {
                        float v = sAV[tid * 33 + j];
                        if (v < mn) { mn = v; mp = j; }
                    }
                    aMin = mn; aPos = mp;
                }
                if (a >= aMin - KMARGIN) {
                    sCand[tid * 132 + clen] = (unsigned char)kk;
                    clen++;
                }
            }
            // phase-b: exact rescore of candidates in recorded (ascending) order
            #pragma unroll 1
            for (int i = 0; i < clen; i++) {
                const int kk = sCand[tid * 132 + i];
                const int key = kt * 128 + kk;
                const float4* kr = (const float4*)(gk + ((size_t)(b * Ll + key)) * Ee + h * 64);
                float acs = 0.0f;
                #pragma unroll
                for (int d4 = 0; d4 < 16; d4++) {
                    float4 kv = kr[d4];
                    acs = fmaf(sQf[tid * 65 + d4 * 4 + 0], kv.x, acs);
                    acs = fmaf(sQf[tid * 65 + d4 * 4 + 1], kv.y, acs);
                    acs = fmaf(sQf[tid * 65 + d4 * 4 + 2], kv.z, acs);
                    acs = fmaf(sQf[tid * 65 + d4 * 4 + 3], kv.w, acs);
                }
                float s = acs * 0.125f;
                if (s > eMin) {
                    sTV[tid * 33 + ePos] = s;
                    sTI[tid * 33 + ePos] = key;
                    float mn = sTV[tid * 33];
                    int   mp = 0;
                    #pragma unroll
                    for (int j = 1; j < TOPKk; j++) {
                        float v = sTV[tid * 33 + j];
                        if (v < mn) { mn = v; mp = j; }
                    }
                    eMin = mn; ePos = mp;
                }
            }
        }
        __syncthreads();
    }

    // epilogue: warp per query softmax + V gather (R8-identical)
    const int warp = tid >> 5;
    for (int qi = warp; qi < 128; qi += 8) {
        float v  = sTV[qi * 33 + lane];
        int   ki = sTI[qi * 33 + lane];

        float mx = v;
        #pragma unroll
        for (int o = 16; o; o >>= 1) mx = fmaxf(mx, __shfl_xor_sync(0xffffffffu, mx, o));
        float e = expf(v - mx);
        float se = e;
        #pragma unroll
        for (int o = 16; o; o >>= 1) se += __shfl_xor_sync(0xffffffffu, se, o);
        float w = e / se;

        float a0 = 0.f, a1 = 0.f;
        #pragma unroll
        for (int j = 0; j < TOPKk; j++) {
            float wj = __shfl_sync(0xffffffffu, w, j);
            int   kj = __shfl_sync(0xffffffffu, ki, j);
            const float* vr = gv + ((size_t)(b * Ll + kj)) * Ee + h * 64;
            a0 = fmaf(wj, vr[lane],      a0);
            a1 = fmaf(wj, vr[lane + 32], a1);
        }
        float* op = gao + ((size_t)(b * Ll + l0 + qi)) * Ee + h * 64;
        op[lane]      = a0;
        op[lane + 32] = a1;
    }
}

// ============================================================
extern "C" void kernel_launch(void* const* d_in, const int* in_sizes, int n_in,
                              void* d_out, int out_size)
{
    const float* Q  = (const float*)d_in[0];
    const float* K_ = (const float*)d_in[1];
    const float* V  = (const float*)d_in[2];
    const float* Wq = (const float*)d_in[3];
    const float* bq = (const float*)d_in[4];
    const float* Wk = (const float*)d_in[5];
    const float* bk = (const float*)d_in[6];
    const float* Wv = (const float*)d_in[7];
    const float* bv = (const float*)d_in[8];
    const float* Wo = (const float*)d_in[9];
    const float* bo = (const float*)d_in[10];
    float* out = (float*)d_out;

    float *gq, *gk, *gv, *gao;
    cudaGetSymbolAddress((void**)&gq,  g_q);
    cudaGetSymbolAddress((void**)&gk,  g_k);
    cudaGetSymbolAddress((void**)&gv,  g_v);
    cudaGetSymbolAddress((void**)&gao, g_ao);
    __nv_bfloat16 *vs1, *vs2, *wv1, *wv2, *wo1, *wo2, *qb, *kb;
    cudaGetSymbolAddress((void**)&vs1, g_vs1);
    cudaGetSymbolAddress((void**)&vs2, g_vs2);
    cudaGetSymbolAddress((void**)&wv1, g_wv1);
    cudaGetSymbolAddress((void**)&wv2, g_wv2);
    cudaGetSymbolAddress((void**)&wo1, g_wo1);
    cudaGetSymbolAddress((void**)&wo2, g_wo2);
    cudaGetSymbolAddress((void**)&qb,  g_qb);
    cudaGetSymbolAddress((void**)&kb,  g_kb);

    static cudaStream_t sV = nullptr;
    static cudaEvent_t eFork = nullptr, eV = nullptr;
    if (sV == nullptr) {
        cudaStreamCreateWithFlags(&sV, cudaStreamNonBlocking);
        cudaEventCreateWithFlags(&eFork, cudaEventDisableTiming);
        cudaEventCreateWithFlags(&eV, cudaEventDisableTiming);
    }

    const int M = Bb * Ll;   // 4096
    const int N = Ee;        // 1024
    const int K = Ee;        // 1024

    dim3 gblock(256);
    dim3 ggrid(N / GBN, M / GBM);
    dim3 tgrid(N / 128, M / 128);

    cudaFuncSetAttribute(gemm_bf16x2_mma,
                         cudaFuncAttributeMaxDynamicSharedMemorySize, TG_SMEM);
    const int faSmem = F_FLOATS * sizeof(float);   // ~199 KB
    cudaFuncSetAttribute(fused_attn_kernel,
                         cudaFuncAttributeMaxDynamicSharedMemorySize, faSmem);

    // ---- fork: v-path on side stream ----
    cudaEventRecord(eFork, 0);
    cudaStreamWaitEvent(sV, eFork, 0);

    split2_kernel<<<(M*K + 255)/256, 256, 0, sV>>>(V,  vs1, vs2, M*K);
    split2_kernel<<<(N*K + 255)/256, 256, 0, sV>>>(Wv, wv1, wv2, N*K);
    gemm_bf16x2_mma<<<tgrid, 256, TG_SMEM, sV>>>(vs1, vs2, wv1, wv2, bv, gv);
    split2_kernel<<<(N*K + 255)/256, 256, 0, sV>>>(Wo, wo1, wo2, N*K);
    cudaEventRecord(eV, sV);

    // ---- main: q, k projections (scalar fp32, bit-identical) ----
    gemm_nt_bias<<<ggrid, gblock>>>(Q,  Wq, bq, gq, M, N, K);
    gemm_nt_bias<<<ggrid, gblock>>>(K_, Wk, bk, gk, M, N, K);

    // bf16 casts for the approx filter
    cast_bf16_kernel<<<(M*K + 255)/256, 256>>>(gq, qb, M*K);
    cast_bf16_kernel<<<(M*K + 255)/256, 256>>>(gk, kb, M*K);

    // join: fused attention needs v from the side stream
    cudaStreamWaitEvent(0, eV, 0);

    dim3 agrid(Ll / 128, Bb * Hh);   // (8, 64)
    fused_attn_kernel<<<agrid, 256, faSmem>>>(gq, gk, gv, qb, kb, gao);

    // ---- output projection (3-term bf16x2) ----
    split2_kernel<<<(M*K + 255)/256, 256>>>(gao, vs1, vs2, M*K);
    gemm_bf16x2_mma<<<tgrid, 256, TG_SMEM>>>(vs1, vs2, wo1, wo2, bo, out);
}

// round 14
// speedup vs baseline: 2.7520x; 1.8854x over previous
#include <cuda_runtime.h>
#include <cuda_bf16.h>
#include <math.h>
#include <stdint.h>

#define Bb 4
#define Ll 1024
#define Ee 1024
#define Hh 16
#define DHh 64
#define TOPKk 32

// -------- scratch (no allocs allowed) --------
__device__ float g_q [Bb*Ll*Ee];
__device__ float g_k [Bb*Ll*Ee];
__device__ float g_v [Bb*Ll*Ee];

// split planes
__device__ __nv_bfloat16 g_vs1[Bb*Ll*Ee];   // V split, then attn-out split
__device__ __nv_bfloat16 g_vs2[Bb*Ll*Ee];
__device__ __nv_bfloat16 g_wv1[Ee*Ee];
__device__ __nv_bfloat16 g_wv2[Ee*Ee];
__device__ __nv_bfloat16 g_wo1[Ee*Ee];
__device__ __nv_bfloat16 g_wo2[Ee*Ee];

// ============================================================
// Scalar fp32 GEMM — exact round-1 version (bit-identical)
// ============================================================
#define GBM 128
#define GBN 128
#define GBK 16

__global__ __launch_bounds__(256) void gemm_nt_bias(
    const float* __restrict__ X, const float* __restrict__ W,
    const float* __restrict__ bias, float* __restrict__ out,
    int M, int N, int K)
{
    __shared__ float As[GBK][GBM];
    __shared__ float Bs[GBK][GBN];

    const int tid = threadIdx.x;
    const int bm = blockIdx.y * GBM;
    const int bn = blockIdx.x * GBN;

    const int tr = (tid / 16) * 8;
    const int tc = (tid % 16) * 8;

    const int arow  = tid >> 2;
    const int acol4 = tid & 3;

    float acc[8][8] = {};

    for (int k0 = 0; k0 < K; k0 += GBK) {
        #pragma unroll
        for (int r = 0; r < 2; r++) {
            int row = arow + r * 64;
            float4 v = *(const float4*)(X + (size_t)(bm + row) * K + k0 + acol4 * 4);
            As[acol4*4+0][row] = v.x;
            As[acol4*4+1][row] = v.y;
            As[acol4*4+2][row] = v.z;
            As[acol4*4+3][row] = v.w;
        }
        #pragma unroll
        for (int r = 0; r < 2; r++) {
            int row = arow + r * 64;
            float4 v = *(const float4*)(W + (size_t)(bn + row) * K + k0 + acol4 * 4);
            Bs[acol4*4+0][row] = v.x;
            Bs[acol4*4+1][row] = v.y;
            Bs[acol4*4+2][row] = v.z;
            Bs[acol4*4+3][row] = v.w;
        }
        __syncthreads();

        #pragma unroll
        for (int k = 0; k < GBK; k++) {
            float ra[8], rb[8];
            #pragma unroll
            for (int i = 0; i < 8; i++) ra[i] = As[k][tr + i];
            #pragma unroll
            for (int j = 0; j < 8; j++) rb[j] = Bs[k][tc + j];
            #pragma unroll
            for (int i = 0; i < 8; i++)
                #pragma unroll
                for (int j = 0; j < 8; j++)
                    acc[i][j] = fmaf(ra[i], rb[j], acc[i][j]);
        }
        __syncthreads();
    }

    #pragma unroll
    for (int i = 0; i < 8; i++) {
        #pragma unroll
        for (int j = 0; j < 8; j++) {
            out[(size_t)(bm + tr + i) * N + bn + tc + j] = acc[i][j] + bias[bn + tc + j];
        }
    }
}

// ============================================================
// bf16x2 split
// ============================================================
__global__ void split2_kernel(const float* __restrict__ src,
                              __nv_bfloat16* __restrict__ p1,
                              __nv_bfloat16* __restrict__ p2, int n)
{
    int i = blockIdx.x * blockDim.x + threadIdx.x;
    if (i >= n) return;
    float x = src[i];
    __nv_bfloat16 b1 = __float2bfloat16_rn(x);
    float r1 = x - __bfloat162float(b1);
    p1[i] = b1;
    p2[i] = __float2bfloat16_rn(r1);
}

// ============================================================
// mma helpers
// ============================================================
__device__ __forceinline__ void mma16816(
    float& d0, float& d1, float& d2, float& d3,
    uint32_t a0, uint32_t a1, uint32_t a2, uint32_t a3,
    uint32_t b0, uint32_t b1)
{
    asm volatile(
        "mma.sync.aligned.m16n8k16.row.col.f32.bf16.bf16.f32 "
        "{%0,%1,%2,%3}, {%4,%5,%6,%7}, {%8,%9}, {%0,%1,%2,%3};"
        : "+f"(d0), "+f"(d1), "+f"(d2), "+f"(d3)
        : "r"(a0), "r"(a1), "r"(a2), "r"(a3), "r"(b0), "r"(b1));
}
__device__ __forceinline__ void ldsm_x4(uint32_t& r0, uint32_t& r1,
                                        uint32_t& r2, uint32_t& r3, uint32_t saddr)
{
    asm volatile("ldmatrix.sync.aligned.m8n8.x4.shared.b16 {%0,%1,%2,%3}, [%4];"
        : "=r"(r0), "=r"(r1), "=r"(r2), "=r"(r3) : "r"(saddr));
}
__device__ __forceinline__ uint32_t smem_u32(const void* p) {
    uint32_t a;
    asm("{ .reg .u64 t; cvta.to.shared.u64 t, %1; cvt.u32.u64 %0, t; }" : "=r"(a) : "l"(p));
    return a;
}
__device__ __forceinline__ void cp_async16(uint32_t saddr, const void* g) {
    asm volatile("cp.async.cg.shared.global [%0], [%1], 16;" :: "r"(saddr), "l"(g));
}
#define CP_COMMIT() asm volatile("cp.async.commit_group;" ::: "memory")
#define CP_WAIT(n)  asm volatile("cp.async.wait_group %0;" :: "n"(n) : "memory")

#define TK 1024
#define TN 1024
#define NCHUNK (TK / 32)
#define SROWB 80
#define TILE_B (128 * SROWB)
#define STAGE_B (4 * TILE_B)
#define TG_SMEM (2 * STAGE_B)

// ============================================================
// 3-term bf16x2 GEMM (v / out projections) — round-7 version
// ============================================================
__global__ __launch_bounds__(256, 2) void gemm_bf16x2_mma(
    const __nv_bfloat16* __restrict__ A1, const __nv_bfloat16* __restrict__ A2,
    const __nv_bfloat16* __restrict__ B1, const __nv_bfloat16* __restrict__ B2,
    const float* __restrict__ bias, float* __restrict__ out)
{
    extern __shared__ char smem[];
    const uint32_t smem_b = smem_u32(smem);

    const int tid = threadIdx.x;
    const int wid = tid >> 5;
    const int lane = tid & 31;
    const int g  = lane >> 2;
    const int tg = lane & 3;

    const int bm = blockIdx.y * 128;
    const int bn = blockIdx.x * 128;
    const int wm = (wid >> 1) * 32;
    const int wn = (wid & 1) * 64;

    const uint32_t lrow = (uint32_t)(lane & 15);
    const uint32_t lcol = (uint32_t)((lane >> 4) << 3);

    const __nv_bfloat16* gp[4] = {A1, A2, B1, B2};
    const int gbase[4] = {bm, bm, bn, bn};

    float acc[2][8][4] = {};

    for (int kc = 0; kc < NCHUNK + 1; kc++) {
        if (kc < NCHUNK) {
            const int k0 = kc * 32;
            const uint32_t stage_off = (uint32_t)(kc & 1) * STAGE_B;
            #pragma unroll
            for (int it = 0; it < 8; it++) {
                int c = tid + it * 256;
                int t = c >> 9;
                int rem = c & 511;
                int row = rem >> 2;
                int seg = rem & 3;
                uint32_t sa = smem_b + stage_off + (uint32_t)t * TILE_B
                            + (uint32_t)row * SROWB + (uint32_t)seg * 16;
                const __nv_bfloat16* gsrc = gp[t] + (size_t)(gbase[t] + row) * TK + k0 + seg * 8;
                cp_async16(sa, gsrc);
            }
            CP_COMMIT();
        }
        if (kc == 0) continue;

        if (kc < NCHUNK) { CP_WAIT(1); } else { CP_WAIT(0); }
        __syncthreads();

        const uint32_t st_u = smem_b + (uint32_t)((kc - 1) & 1) * STAGE_B;

        #pragma unroll
        for (int ks = 0; ks < 2; ks++) {
            const uint32_t coff = (uint32_t)(ks * 16) * 2 + lcol * 2;

            uint32_t af[2][2][4];
            #pragma unroll
            for (int p = 0; p < 2; p++)
                #pragma unroll
                for (int mt = 0; mt < 2; mt++) {
                    uint32_t addr = st_u + (uint32_t)p * TILE_B
                                  + ((uint32_t)(wm + mt * 16) + lrow) * SROWB + coff;
                    ldsm_x4(af[p][mt][0], af[p][mt][1], af[p][mt][2], af[p][mt][3], addr);
                }
            #pragma unroll
            for (int np = 0; np < 4; np++) {
                uint32_t bf[2][2][2];
                #pragma unroll
                for (int p = 0; p < 2; p++) {
                    uint32_t addr = st_u + (uint32_t)(2 + p) * TILE_B
                                  + ((uint32_t)(wn + np * 16) + lrow) * SROWB + coff;
                    ldsm_x4(bf[p][0][0], bf[p][1][0], bf[p][0][1], bf[p][1][1], addr);
                }
                #pragma unroll
                for (int ntl = 0; ntl < 2; ntl++) {
                    const int nt = np * 2 + ntl;
                    #pragma unroll
                    for (int mt = 0; mt < 2; mt++) {
                        mma16816(acc[mt][nt][0], acc[mt][nt][1], acc[mt][nt][2], acc[mt][nt][3],
                                 af[0][mt][0], af[0][mt][1], af[0][mt][2], af[0][mt][3],
                                 bf[0][ntl][0], bf[0][ntl][1]);
                        mma16816(acc[mt][nt][0], acc[mt][nt][1], acc[mt][nt][2], acc[mt][nt][3],
                                 af[0][mt][0], af[0][mt][1], af[0][mt][2], af[0][mt][3],
                                 bf[1][ntl][0], bf[1][ntl][1]);
                        mma16816(acc[mt][nt][0], acc[mt][nt][1], acc[mt][nt][2], acc[mt][nt][3],
                                 af[1][mt][0], af[1][mt][1], af[1][mt][2], af[1][mt][3],
                                 bf[0][ntl][0], bf[0][ntl][1]);
                    }
                }
            }
        }
        __syncthreads();
    }

    #pragma unroll
    for (int mt = 0; mt < 2; mt++) {
        #pragma unroll
        for (int nt = 0; nt < 8; nt++) {
            int m0 = bm + wm + mt * 16 + g;
            int n0 = bn + wn + nt * 8 + tg * 2;
            float b0 = bias[n0], b1 = bias[n0 + 1];
            float2 lo = make_float2(acc[mt][nt][0] + b0, acc[mt][nt][1] + b1);
            float2 hi = make_float2(acc[mt][nt][2] + b0, acc[mt][nt][3] + b1);
            *(float2*)(out + (size_t)m0 * TN + n0)       = lo;
            *(float2*)(out + (size_t)(m0 + 8) * TN + n0) = hi;
        }
    }
}

// ============================================================
// Attention (R8 structure; deferred-insert scan via bitmask —
// bit-identical selection; epilogue writes bf16x2 split directly)
// ============================================================
#define ATT_QT 128
#define ATT_KT 32
#define ATT_THREADS 256

#define SM_QT   0
#define SM_KT   (SM_QT + 64*128)
#define SM_S    (SM_KT + 64*ATT_KT)
#define SM_TV   (SM_S  + 128*33)
#define SM_TI   (SM_TV + 128*33)
#define ATT_SMEM_FLOATS (SM_TI + 128*33)

__global__ __launch_bounds__(ATT_THREADS) void attn_topk_kernel(
    const float* __restrict__ gq, const float* __restrict__ gk,
    const float* __restrict__ gv,
    __nv_bfloat16* __restrict__ ao1, __nv_bfloat16* __restrict__ ao2)
{
    extern __shared__ float sm[];
    float* sQt = sm + SM_QT;
    float* sKt = sm + SM_KT;
    float* sS  = sm + SM_S;
    float* sTV = sm + SM_TV;
    int*   sTI = (int*)(sm + SM_TI);

    const int tid = threadIdx.x;
    const int bh  = blockIdx.y;
    const int b   = bh / Hh;
    const int h   = bh % Hh;
    const int l0  = blockIdx.x * ATT_QT;

    for (int idx = tid; idx < ATT_QT * DHh; idx += ATT_THREADS) {
        int qq = idx >> 6;
        int d  = idx & 63;
        sQt[d * ATT_QT + qq] = gq[((size_t)(b * Ll + l0 + qq)) * Ee + h * DHh + d];
    }

    if (tid < 128) {
        #pragma unroll
        for (int j = 0; j < TOPKk; j++) {
            sTV[tid * 33 + j] = -INFINITY;
            sTI[tid * 33 + j] = 0;
        }
    }
    float curMin = -INFINITY;
    int   curPos = 0;

    const int ty = tid >> 3;  // 0..31 (query group of 4)
    const int tx = tid & 7;   // 0..7  (key group of 4)

    for (int kt = 0; kt < Ll / ATT_KT; kt++) {
        for (int idx = tid; idx < ATT_KT * DHh; idx += ATT_THREADS) {
            int kk = idx >> 6;
            int d  = idx & 63;
            sKt[d * ATT_KT + kk] = gk[((size_t)(b * Ll + kt * ATT_KT + kk)) * Ee + h * DHh + d];
        }
        __syncthreads();

        // 128x32 score tile, 4x4 per thread (same per-output d-ascending fma chain)
        float acc[4][4] = {};
        #pragma unroll 8
        for (int d = 0; d < DHh; d++) {
            float ra[4], rb[4];
            *(float4*)&ra[0] = *(const float4*)&sQt[d * ATT_QT + ty * 4];
            *(float4*)&rb[0] = *(const float4*)&sKt[d * ATT_KT + tx * 4];
            #pragma unroll
            for (int i = 0; i < 4; i++)
                #pragma unroll
                for (int j = 0; j < 4; j++)
                    acc[i][j] = fmaf(ra[i], rb[j], acc[i][j]);
        }
        #pragma unroll
        for (int i = 0; i < 4; i++)
            #pragma unroll
            for (int j = 0; j < 4; j++)
                sS[(ty * 4 + i) * 33 + tx * 4 + j] = acc[i][j] * 0.125f;
        __syncthreads();

        if (tid < 128) {
            // phase a: stale-gated mask build (no divergent body).
            // curMin only grows during inserts, so gate(stale) superset
            // of gate(live) -> identical live insert sequence as R8.
            unsigned int mask = 0;
            const float gateMin = curMin;
            #pragma unroll
            for (int kk = 0; kk < ATT_KT; kk++) {
                float s = sS[tid * 33 + kk];
                if (s > gateMin) mask |= (1u << kk);
            }
            // phase b: live insert in ascending-key order (bit-identical)
            while (mask) {
                const int kk = __ffs(mask) - 1;
                mask &= mask - 1;
                float s = sS[tid * 33 + kk];
                if (s > curMin) {
                    sTV[tid * 33 + curPos] = s;
                    sTI[tid * 33 + curPos] = kt * ATT_KT + kk;
                    float mn = sTV[tid * 33];
                    int   mp = 0;
                    #pragma unroll
                    for (int j = 1; j < TOPKk; j++) {
                        float v = sTV[tid * 33 + j];
                        if (v < mn) { mn = v; mp = j; }
                    }
                    curMin = mn; curPos = mp;
                }
            }
        }
        __syncthreads();
    }

    // epilogue: warp per query softmax + V gather; write bf16x2 split
    const int warp = tid >> 5;
    const int lane = tid & 31;
    for (int qi = warp; qi < ATT_QT; qi += 8) {
        float v  = sTV[qi * 33 + lane];
        int   ki = sTI[qi * 33 + lane];

        float mx = v;
        #pragma unroll
        for (int o = 16; o; o >>= 1) mx = fmaxf(mx, __shfl_xor_sync(0xffffffffu, mx, o));
        float e = expf(v - mx);
        float se = e;
        #pragma unroll
        for (int o = 16; o; o >>= 1) se += __shfl_xor_sync(0xffffffffu, se, o);
        float w = e / se;

        float a0 = 0.f, a1 = 0.f;
        #pragma unroll
        for (int j = 0; j < TOPKk; j++) {
            float wj = __shfl_sync(0xffffffffu, w, j);
            int   kj = __shfl_sync(0xffffffffu, ki, j);
            const float* vr = gv + ((size_t)(b * Ll + kj)) * Ee + h * DHh;
            a0 = fmaf(wj, vr[lane],      a0);
            a1 = fmaf(wj, vr[lane + 32], a1);
        }
        // split2 fused: same arithmetic as split2_kernel on gao
        size_t base = ((size_t)(b * Ll + l0 + qi)) * Ee + h * DHh;
        __nv_bfloat16 b0 = __float2bfloat16_rn(a0);
        ao1[base + lane]      = b0;
        ao2[base + lane]      = __float2bfloat16_rn(a0 - __bfloat162float(b0));
        __nv_bfloat16 b1h = __float2bfloat16_rn(a1);
        ao1[base + lane + 32] = b1h;
        ao2[base + lane + 32] = __float2bfloat16_rn(a1 - __bfloat162float(b1h));
    }
}

// ============================================================
extern "C" void kernel_launch(void* const* d_in, const int* in_sizes, int n_in,
                              void* d_out, int out_size)
{
    const float* Q  = (const float*)d_in[0];
    const float* K_ = (const float*)d_in[1];
    const float* V  = (const float*)d_in[2];
    const float* Wq = (const float*)d_in[3];
    const float* bq = (const float*)d_in[4];
    const float* Wk = (const float*)d_in[5];
    const float* bk = (const float*)d_in[6];
    const float* Wv = (const float*)d_in[7];
    const float* bv = (const float*)d_in[8];
    const float* Wo = (const float*)d_in[9];
    const float* bo = (const float*)d_in[10];
    float* out = (float*)d_out;

    float *gq, *gk, *gv;
    cudaGetSymbolAddress((void**)&gq,  g_q);
    cudaGetSymbolAddress((void**)&gk,  g_k);
    cudaGetSymbolAddress((void**)&gv,  g_v);
    __nv_bfloat16 *vs1, *vs2, *wv1, *wv2, *wo1, *wo2;
    cudaGetSymbolAddress((void**)&vs1, g_vs1);
    cudaGetSymbolAddress((void**)&vs2, g_vs2);
    cudaGetSymbolAddress((void**)&wv1, g_wv1);
    cudaGetSymbolAddress((void**)&wv2, g_wv2);
    cudaGetSymbolAddress((void**)&wo1, g_wo1);
    cudaGetSymbolAddress((void**)&wo2, g_wo2);

    static cudaStream_t sV = nullptr;
    static cudaEvent_t eFork = nullptr, eV = nullptr;
    if (sV == nullptr) {
        cudaStreamCreateWithFlags(&sV, cudaStreamNonBlocking);
        cudaEventCreateWithFlags(&eFork, cudaEventDisableTiming);
        cudaEventCreateWithFlags(&eV, cudaEventDisableTiming);
    }

    const int M = Bb * Ll;
    const int N = Ee;
    const int K = Ee;

    dim3 gblock(256);
    dim3 ggrid(N / GBN, M / GBM);
    dim3 tgrid(N / 128, M / 128);

    cudaFuncSetAttribute(gemm_bf16x2_mma,
                         cudaFuncAttributeMaxDynamicSharedMemorySize, TG_SMEM);
    size_t attSmem = ATT_SMEM_FLOATS * sizeof(float);
    cudaFuncSetAttribute(attn_topk_kernel,
                         cudaFuncAttributeMaxDynamicSharedMemorySize, (int)attSmem);

    // ---- fork: v-path runs concurrently with q/k scalar GEMMs ----
    cudaEventRecord(eFork, 0);
    cudaStreamWaitEvent(sV, eFork, 0);

    split2_kernel<<<(M*K + 255)/256, 256, 0, sV>>>(V,  vs1, vs2, M*K);
    split2_kernel<<<(N*K + 255)/256, 256, 0, sV>>>(Wv, wv1, wv2, N*K);
    gemm_bf16x2_mma<<<tgrid, 256, TG_SMEM, sV>>>(vs1, vs2, wv1, wv2, bv, gv);
    split2_kernel<<<(N*K + 255)/256, 256, 0, sV>>>(Wo, wo1, wo2, N*K);
    cudaEventRecord(eV, sV);

    // ---- main: q, k projections (scalar fp32, bit-identical) ----
    gemm_nt_bias<<<ggrid, gblock>>>(Q,  Wq, bq, gq, M, N, K);
    gemm_nt_bias<<<ggrid, gblock>>>(K_, Wk, bk, gk, M, N, K);

    // ---- join: attention needs q, k (main) and v (side) ----
    // (v-GEMM has consumed vs1/vs2 before eV, so attn may overwrite them)
    cudaStreamWaitEvent(0, eV, 0);

    dim3 agrid(Ll / ATT_QT, Bb * Hh);
    attn_topk_kernel<<<agrid, ATT_THREADS, attSmem>>>(gq, gk, gv, vs1, vs2);

    // ---- output projection (3-term bf16x2), split fused into attn ----
    gemm_bf16x2_mma<<<tgrid, 256, TG_SMEM>>>(vs1, vs2, wo1, wo2, bo, out);
}